// round 1
// baseline (speedup 1.0000x reference)
#include <cuda_runtime.h>
#include <math.h>

#define Bb 8
#define Tt 12
#define Nn 307
#define Dd 64
#define Hh 4
#define HDm 16
#define NSLICE (Hh*Bb*Tt)        /* 384 */
#define NN (Nn*Nn)               /* 94249 */
#define BTN (Bb*Tt*Nn)           /* 29472 */
#define BTND (BTN*Dd)            /* 1886208 */

// ---------------- scratch (static device globals; no allocs) ----------------
__device__ float g_nadj[NN];
__device__ float g_q2[BTND];
__device__ float g_k2[BTND];
__device__ float g_v2[BTND];
__device__ float g_qt[BTND];
__device__ float g_out1h[BTND];                 // 0.5*relu(graphconv)
__device__ float g_P[(size_t)NSLICE*NN];        // softmax(relu(YY^T/8))
__device__ float g_dyn[(size_t)NSLICE*NN];      // P @ E_g

// ---------------- kernel 1: normalized adjacency ----------------
__global__ void nadj_kernel(const float* __restrict__ adj) {
    int i = blockIdx.x;
    __shared__ float red[256];
    float s = 0.f;
    for (int j = threadIdx.x; j < Nn; j += 256) s += adj[i*Nn + j];
    red[threadIdx.x] = s; __syncthreads();
    for (int w = 128; w > 0; w >>= 1) {
        if (threadIdx.x < w) red[threadIdx.x] += red[threadIdx.x + w];
        __syncthreads();
    }
    float inv = 1.f / (red[0] + 1.f);   // +1 for the identity diagonal
    for (int j = threadIdx.x; j < Nn; j += 256) {
        float v = adj[i*Nn + j] + (j == i ? 1.f : 0.f);
        g_nadj[i*Nn + j] = v * inv;
    }
}

// ---------------- kernel 2: batched linear X @ W^T (+ bias) ----------------
// blockIdx.z: 0->q2 (Wq,bq), 1->k2 (Wk,bk), 2->v2 (Wv,bv), 3->qt (Wt, no bias)
__global__ void linear_kernel(const float* __restrict__ query,
                              const float* __restrict__ key_in,
                              const float* __restrict__ value,
                              const float* __restrict__ Wq, const float* __restrict__ bq,
                              const float* __restrict__ Wk, const float* __restrict__ bk,
                              const float* __restrict__ Wv, const float* __restrict__ bv,
                              const float* __restrict__ Wt) {
    int which = blockIdx.z;
    const float* X; const float* W; const float* bias; float* out;
    if (which == 0)      { X = query;  W = Wq; bias = bq;      out = g_q2; }
    else if (which == 1) { X = key_in; W = Wk; bias = bk;      out = g_k2; }
    else if (which == 2) { X = value;  W = Wv; bias = bv;      out = g_v2; }
    else                 { X = query;  W = Wt; bias = nullptr; out = g_qt; }

    __shared__ float Xs[64][65];
    __shared__ float Wts[64][65];   // Wts[k][j] = W[j][k]
    int tid = threadIdx.x;
    int rowBase = blockIdx.x * 64;
    int rows = min(64, BTN - rowBase);

    for (int idx = tid; idx < 64*64; idx += 256) {
        int r = idx >> 6, c = idx & 63;
        Xs[r][c] = (r < rows) ? X[(size_t)(rowBase + r)*64 + c] : 0.f;
    }
    for (int idx = tid; idx < 64*64; idx += 256) {
        int j = idx >> 6, k = idx & 63;
        Wts[k][j] = W[idx];
    }
    __syncthreads();

    int ty = tid >> 4, tx = tid & 15;
    int r0 = ty*4, c0 = tx*4;
    float acc[4][4] = {};
    for (int k = 0; k < 64; k++) {
        float a[4], b4[4];
        #pragma unroll
        for (int i = 0; i < 4; i++) a[i] = Xs[r0 + i][k];
        #pragma unroll
        for (int j = 0; j < 4; j++) b4[j] = Wts[k][c0 + j];
        #pragma unroll
        for (int i = 0; i < 4; i++)
            #pragma unroll
            for (int j = 0; j < 4; j++) acc[i][j] += a[i]*b4[j];
    }
    #pragma unroll
    for (int i = 0; i < 4; i++) {
        int r = r0 + i;
        if (r < rows) {
            #pragma unroll
            for (int j = 0; j < 4; j++) {
                float v = acc[i][j];
                if (bias) v += bias[c0 + j];
                out[(size_t)(rowBase + r)*64 + c0 + j] = v;
            }
        }
    }
}

// ---------------- kernel 3: graph conv: 0.5*relu(nadj @ qt + bt) ----------------
// grid (5, 96): x = row tile of 64, y = (b*T+t)
__global__ void graphconv_kernel(const float* __restrict__ bt_bias) {
    int bt = blockIdx.y;
    int rowBase = blockIdx.x * 64;
    const float* Bm = g_qt + (size_t)bt*Nn*Dd;
    float* out = g_out1h + (size_t)bt*Nn*Dd;

    __shared__ float As[16][68];
    __shared__ float Bs[16][68];
    int tid = threadIdx.x;
    int ty = tid >> 4, tx = tid & 15;
    int r0 = ty*4, c0 = tx*4;
    float acc[4][4] = {};

    for (int kt = 0; kt < Nn; kt += 16) {
        for (int idx = tid; idx < 64*16; idx += 256) {
            int kk = idx & 15, m = idx >> 4;
            int gr = rowBase + m, gk = kt + kk;
            As[kk][m] = (gr < Nn && gk < Nn) ? g_nadj[(size_t)gr*Nn + gk] : 0.f;
        }
        for (int idx = tid; idx < 64*16; idx += 256) {
            int n = idx & 63, kk = idx >> 6;
            int gk = kt + kk;
            Bs[kk][n] = (gk < Nn) ? Bm[(size_t)gk*64 + n] : 0.f;
        }
        __syncthreads();
        #pragma unroll
        for (int k = 0; k < 16; k++) {
            float4 av = *(const float4*)&As[k][r0];
            float4 bv = *(const float4*)&Bs[k][c0];
            float a[4] = {av.x, av.y, av.z, av.w};
            float b4[4] = {bv.x, bv.y, bv.z, bv.w};
            #pragma unroll
            for (int i = 0; i < 4; i++)
                #pragma unroll
                for (int j = 0; j < 4; j++) acc[i][j] += a[i]*b4[j];
        }
        __syncthreads();
    }
    #pragma unroll
    for (int i = 0; i < 4; i++) {
        int r = rowBase + r0 + i;
        if (r < Nn) {
            #pragma unroll
            for (int j = 0; j < 4; j++) {
                int c = c0 + j;
                float v = acc[i][j] + bt_bias[c];
                out[(size_t)r*64 + c] = 0.5f * fmaxf(v, 0.f);
            }
        }
    }
}

// ---------------- kernel 4: P = softmax(relu(Y Y^T / 8)) per slice ----------------
// grid (4, 384); block 256 (8 warps), warp-per-row
__global__ void pmat_kernel(const float* __restrict__ query) {
    int slice = blockIdx.y;
    int hb = slice / Tt, t = slice % Tt;
    int h = hb / Bb, b = hb % Bb;
    __shared__ float Ys[Nn*17];
    const float* qbase = query + ((size_t)(b*Tt + t)*Nn)*Dd + h*HDm;
    for (int idx = threadIdx.x; idx < Nn*HDm; idx += 256) {
        int n = idx >> 4, d = idx & 15;
        Ys[n*17 + d] = qbase[(size_t)n*Dd + d];
    }
    __syncthreads();

    int warp = threadIdx.x >> 5, lane = threadIdx.x & 31;
    int rstart = blockIdx.x * 77;
    int rend = min(Nn, rstart + 77);
    float* Pb = g_P + (size_t)slice*NN;

    for (int n = rstart + warp; n < rend; n += 8) {
        float qn[16];
        #pragma unroll
        for (int d = 0; d < 16; d++) qn[d] = Ys[n*17 + d];
        float e[10]; float mx = -1e30f;
        #pragma unroll
        for (int k = 0; k < 10; k++) {
            int m = lane + 32*k;
            float s = -1e30f;
            if (m < Nn) {
                float a = 0.f;
                #pragma unroll
                for (int d = 0; d < 16; d++) a += qn[d]*Ys[m*17 + d];
                s = fmaxf(a * 0.125f, 0.f);
            }
            e[k] = s; mx = fmaxf(mx, s);
        }
        #pragma unroll
        for (int o = 16; o; o >>= 1) mx = fmaxf(mx, __shfl_xor_sync(0xffffffffu, mx, o));
        float sum = 0.f;
        #pragma unroll
        for (int k = 0; k < 10; k++) { float v = __expf(e[k] - mx); e[k] = v; sum += v; }
        #pragma unroll
        for (int o = 16; o; o >>= 1) sum += __shfl_xor_sync(0xffffffffu, sum, o);
        float inv = 1.f / sum;
        #pragma unroll
        for (int k = 0; k < 10; k++) {
            int m = lane + 32*k;
            if (m < Nn) Pb[(size_t)n*Nn + m] = e[k]*inv;
        }
    }
}

// ---------------- kernel 5: dyn = P @ E_g (batched 307^3 SGEMM) ----------------
// grid (5, 5, 384); 64x64 tile, BK=16, 4x4 micro-tile
__global__ void dyn_gemm_kernel(const float* __restrict__ Eg) {
    int slice = blockIdx.z;
    const float* A = g_P + (size_t)slice*NN;
    float* C = g_dyn + (size_t)slice*NN;
    int rowBase = blockIdx.y * 64, colBase = blockIdx.x * 64;

    __shared__ float As[16][68];
    __shared__ float Bs[16][68];
    int tid = threadIdx.x;
    int ty = tid >> 4, tx = tid & 15;
    int r0 = ty*4, c0 = tx*4;
    float acc[4][4] = {};

    for (int kt = 0; kt < Nn; kt += 16) {
        for (int idx = tid; idx < 64*16; idx += 256) {
            int kk = idx & 15, m = idx >> 4;
            int gr = rowBase + m, gk = kt + kk;
            As[kk][m] = (gr < Nn && gk < Nn) ? A[(size_t)gr*Nn + gk] : 0.f;
        }
        for (int idx = tid; idx < 64*16; idx += 256) {
            int n = idx & 63, kk = idx >> 6;
            int gk = kt + kk, gc = colBase + n;
            Bs[kk][n] = (gk < Nn && gc < Nn) ? Eg[(size_t)gk*Nn + gc] : 0.f;
        }
        __syncthreads();
        #pragma unroll
        for (int k = 0; k < 16; k++) {
            float4 av = *(const float4*)&As[k][r0];
            float4 bv = *(const float4*)&Bs[k][c0];
            float a[4] = {av.x, av.y, av.z, av.w};
            float b4[4] = {bv.x, bv.y, bv.z, bv.w};
            #pragma unroll
            for (int i = 0; i < 4; i++)
                #pragma unroll
                for (int j = 0; j < 4; j++) acc[i][j] += a[i]*b4[j];
        }
        __syncthreads();
    }
    #pragma unroll
    for (int i = 0; i < 4; i++) {
        int r = rowBase + r0 + i;
        if (r < Nn) {
            #pragma unroll
            for (int j = 0; j < 4; j++) {
                int c = colBase + c0 + j;
                if (c < Nn) C[(size_t)r*Nn + c] = acc[i][j];
            }
        }
    }
}

// ---------------- kernel 6: attention + tanh + merge + combine ----------------
// grid (4, 384); warp-per-row
__global__ void attn_kernel(float* __restrict__ out) {
    int slice = blockIdx.y;
    int hb = slice / Tt, t = slice % Tt;
    int h = hb / Bb, b = hb % Bb;
    __shared__ float Ks[Nn*17];
    __shared__ float Vs[Nn*17];
    size_t sl_off = ((size_t)(b*Tt + t)*Nn)*Dd + h*HDm;
    const float* kbase = g_k2 + sl_off;
    const float* vbase = g_v2 + sl_off;
    const float* qbase = g_q2 + sl_off;
    for (int idx = threadIdx.x; idx < Nn*HDm; idx += 256) {
        int n = idx >> 4, d = idx & 15;
        Ks[n*17 + d] = kbase[(size_t)n*Dd + d];
        Vs[n*17 + d] = vbase[(size_t)n*Dd + d];
    }
    __syncthreads();

    int warp = threadIdx.x >> 5, lane = threadIdx.x & 31;
    int rstart = blockIdx.x * 77;
    int rend = min(Nn, rstart + 77);
    const float* dynb = g_dyn + (size_t)slice*NN;

    for (int n = rstart + warp; n < rend; n += 8) {
        float qn[16];
        #pragma unroll
        for (int d = 0; d < 16; d++) qn[d] = qbase[(size_t)n*Dd + d];
        float e[10]; float mx = -1e30f;
        #pragma unroll
        for (int k = 0; k < 10; k++) {
            int m = lane + 32*k;
            float s = -1e30f;
            if (m < Nn) {
                float a = 0.f;
                #pragma unroll
                for (int d = 0; d < 16; d++) a += qn[d]*Ks[m*17 + d];
                s = (a * 0.25f) * dynb[(size_t)n*Nn + m];
            }
            e[k] = s; mx = fmaxf(mx, s);
        }
        #pragma unroll
        for (int o = 16; o; o >>= 1) mx = fmaxf(mx, __shfl_xor_sync(0xffffffffu, mx, o));
        float sum = 0.f;
        #pragma unroll
        for (int k = 0; k < 10; k++) { float v = __expf(e[k] - mx); e[k] = v; sum += v; }
        #pragma unroll
        for (int o = 16; o; o >>= 1) sum += __shfl_xor_sync(0xffffffffu, sum, o);
        float inv = 1.f / sum;

        float acc[16];
        #pragma unroll
        for (int d = 0; d < 16; d++) acc[d] = 0.f;
        #pragma unroll
        for (int k = 0; k < 10; k++) {
            int m = lane + 32*k;
            if (m < Nn) {
                float w = e[k]*inv;
                #pragma unroll
                for (int d = 0; d < 16; d++) acc[d] += w * Vs[m*17 + d];
            }
        }
        #pragma unroll
        for (int d = 0; d < 16; d++) {
            #pragma unroll
            for (int o = 16; o; o >>= 1) acc[d] += __shfl_xor_sync(0xffffffffu, acc[d], o);
        }
        if (lane < 16) {
            size_t oidx = ((size_t)(b*Tt + t)*Nn + n)*Dd + h*HDm + lane;
            out[oidx] = g_out1h[oidx] + 0.5f * tanhf(acc[lane]);
        }
    }
}

// ---------------- launch ----------------
extern "C" void kernel_launch(void* const* d_in, const int* in_sizes, int n_in,
                              void* d_out, int out_size) {
    const float* query  = (const float*)d_in[0];
    const float* key_in = (const float*)d_in[1];
    const float* value  = (const float*)d_in[2];
    const float* adj    = (const float*)d_in[3];
    const float* Eg     = (const float*)d_in[4];
    const float* Wq     = (const float*)d_in[5];
    const float* bq     = (const float*)d_in[6];
    const float* Wk     = (const float*)d_in[7];
    const float* bk     = (const float*)d_in[8];
    const float* Wv     = (const float*)d_in[9];
    const float* bv     = (const float*)d_in[10];
    const float* Wt     = (const float*)d_in[11];
    const float* bt     = (const float*)d_in[12];
    float* out = (float*)d_out;

    nadj_kernel<<<Nn, 256>>>(adj);
    linear_kernel<<<dim3((BTN + 63)/64, 1, 4), 256>>>(query, key_in, value,
                                                      Wq, bq, Wk, bk, Wv, bv, Wt);
    graphconv_kernel<<<dim3(5, Bb*Tt), 256>>>(bt);
    pmat_kernel<<<dim3(4, NSLICE), 256>>>(query);
    dyn_gemm_kernel<<<dim3(5, 5, NSLICE), 256>>>(Eg);
    attn_kernel<<<dim3(4, NSLICE), 256>>>(out);
}

// round 2
// speedup vs baseline: 1.5277x; 1.5277x over previous
#include <cuda_runtime.h>
#include <math.h>

#define Bb 8
#define Tt 12
#define Nn 307
#define Dd 64
#define Hh 4
#define HDm 16
#define NSLICE (Hh*Bb*Tt)        /* 384 */
#define NN (Nn*Nn)               /* 94249 */
#define BTN (Bb*Tt*Nn)           /* 29472 */
#define BTND (BTN*Dd)            /* 1886208 */

#define LDP 320                  /* padded inner stride for P/dyn/EgP */
#define MR  384                  /* padded row count for P/dyn */
#define SLICE_CP (MR*LDP)        /* 122880 floats per slice */

// ---------------- scratch (static device globals; zero-init, no allocs) ----
__device__ float g_nadj[NN];
__device__ float g_q2[BTND];
__device__ float g_k2[BTND];
__device__ float g_v2[BTND];
__device__ float g_qt[BTND];
__device__ float g_out1h[BTND];                    // 0.5*relu(graphconv)
__device__ float g_P[(size_t)NSLICE*SLICE_CP];     // padded softmax(relu(YY^T/8))
__device__ float g_dyn[(size_t)NSLICE*SLICE_CP];   // padded P @ E_g
__device__ float g_EgP[LDP*LDP];                   // padded E_g

__device__ __forceinline__ unsigned f2tf(float f) {
    unsigned u;
    asm("cvt.rna.tf32.f32 %0, %1;" : "=r"(u) : "f"(f));
    return u;
}

// ---------------- kernel 1: normalized adjacency ----------------
__global__ void nadj_kernel(const float* __restrict__ adj) {
    int i = blockIdx.x;
    __shared__ float red[256];
    float s = 0.f;
    for (int j = threadIdx.x; j < Nn; j += 256) s += adj[i*Nn + j];
    red[threadIdx.x] = s; __syncthreads();
    for (int w = 128; w > 0; w >>= 1) {
        if (threadIdx.x < w) red[threadIdx.x] += red[threadIdx.x + w];
        __syncthreads();
    }
    float inv = 1.f / (red[0] + 1.f);   // +1 for the identity diagonal
    for (int j = threadIdx.x; j < Nn; j += 256) {
        float v = adj[i*Nn + j] + (j == i ? 1.f : 0.f);
        g_nadj[i*Nn + j] = v * inv;
    }
}

// ---------------- kernel 1b: pack E_g into padded [320][320] ----------------
__global__ void egpack_kernel(const float* __restrict__ Eg) {
    int r = blockIdx.x;                // 0..319
    for (int c = threadIdx.x; c < LDP; c += 256) {
        float v = (r < Nn && c < Nn) ? Eg[r*Nn + c] : 0.f;
        g_EgP[r*LDP + c] = v;
    }
}

// ---------------- kernel 2: batched linear X @ W^T (+ bias) ----------------
__global__ void linear_kernel(const float* __restrict__ query,
                              const float* __restrict__ key_in,
                              const float* __restrict__ value,
                              const float* __restrict__ Wq, const float* __restrict__ bq,
                              const float* __restrict__ Wk, const float* __restrict__ bk,
                              const float* __restrict__ Wv, const float* __restrict__ bv,
                              const float* __restrict__ Wt) {
    int which = blockIdx.z;
    const float* X; const float* W; const float* bias; float* out;
    if (which == 0)      { X = query;  W = Wq; bias = bq;      out = g_q2; }
    else if (which == 1) { X = key_in; W = Wk; bias = bk;      out = g_k2; }
    else if (which == 2) { X = value;  W = Wv; bias = bv;      out = g_v2; }
    else                 { X = query;  W = Wt; bias = nullptr; out = g_qt; }

    __shared__ float Xs[64][65];
    __shared__ float Wts[64][65];
    int tid = threadIdx.x;
    int rowBase = blockIdx.x * 64;
    int rows = min(64, BTN - rowBase);

    for (int idx = tid; idx < 64*64; idx += 256) {
        int r = idx >> 6, c = idx & 63;
        Xs[r][c] = (r < rows) ? X[(size_t)(rowBase + r)*64 + c] : 0.f;
    }
    for (int idx = tid; idx < 64*64; idx += 256) {
        int j = idx >> 6, k = idx & 63;
        Wts[k][j] = W[idx];
    }
    __syncthreads();

    int ty = tid >> 4, tx = tid & 15;
    int r0 = ty*4, c0 = tx*4;
    float acc[4][4] = {};
    for (int k = 0; k < 64; k++) {
        float a[4], b4[4];
        #pragma unroll
        for (int i = 0; i < 4; i++) a[i] = Xs[r0 + i][k];
        #pragma unroll
        for (int j = 0; j < 4; j++) b4[j] = Wts[k][c0 + j];
        #pragma unroll
        for (int i = 0; i < 4; i++)
            #pragma unroll
            for (int j = 0; j < 4; j++) acc[i][j] += a[i]*b4[j];
    }
    #pragma unroll
    for (int i = 0; i < 4; i++) {
        int r = r0 + i;
        if (r < rows) {
            #pragma unroll
            for (int j = 0; j < 4; j++) {
                float v = acc[i][j];
                if (bias) v += bias[c0 + j];
                out[(size_t)(rowBase + r)*64 + c0 + j] = v;
            }
        }
    }
}

// ---------------- kernel 3: graph conv: 0.5*relu(nadj @ qt + bt) ----------------
__global__ void graphconv_kernel(const float* __restrict__ bt_bias) {
    int bt = blockIdx.y;
    int rowBase = blockIdx.x * 64;
    const float* Bm = g_qt + (size_t)bt*Nn*Dd;
    float* out = g_out1h + (size_t)bt*Nn*Dd;

    __shared__ float As[16][68];
    __shared__ float Bs[16][68];
    int tid = threadIdx.x;
    int ty = tid >> 4, tx = tid & 15;
    int r0 = ty*4, c0 = tx*4;
    float acc[4][4] = {};

    for (int kt = 0; kt < Nn; kt += 16) {
        for (int idx = tid; idx < 64*16; idx += 256) {
            int kk = idx & 15, m = idx >> 4;
            int gr = rowBase + m, gk = kt + kk;
            As[kk][m] = (gr < Nn && gk < Nn) ? g_nadj[(size_t)gr*Nn + gk] : 0.f;
        }
        for (int idx = tid; idx < 64*16; idx += 256) {
            int n = idx & 63, kk = idx >> 6;
            int gk = kt + kk;
            Bs[kk][n] = (gk < Nn) ? Bm[(size_t)gk*64 + n] : 0.f;
        }
        __syncthreads();
        #pragma unroll
        for (int k = 0; k < 16; k++) {
            float4 av = *(const float4*)&As[k][r0];
            float4 bv = *(const float4*)&Bs[k][c0];
            float a[4] = {av.x, av.y, av.z, av.w};
            float b4[4] = {bv.x, bv.y, bv.z, bv.w};
            #pragma unroll
            for (int i = 0; i < 4; i++)
                #pragma unroll
                for (int j = 0; j < 4; j++) acc[i][j] += a[i]*b4[j];
        }
        __syncthreads();
    }
    #pragma unroll
    for (int i = 0; i < 4; i++) {
        int r = rowBase + r0 + i;
        if (r < Nn) {
            #pragma unroll
            for (int j = 0; j < 4; j++) {
                int c = c0 + j;
                float v = acc[i][j] + bt_bias[c];
                out[(size_t)r*64 + c] = 0.5f * fmaxf(v, 0.f);
            }
        }
    }
}

// ---------------- kernel 4: P = softmax(relu(Y Y^T / 8)) per slice ----------------
// writes padded rows [n][0..319], pad cols get exact zeros
__global__ __launch_bounds__(256, 2) void pmat_kernel(const float* __restrict__ query) {
    int slice = blockIdx.y;
    int hb = slice / Tt, t = slice % Tt;
    int h = hb / Bb, b = hb % Bb;
    __shared__ float Ys[Nn*17];
    const float* qbase = query + ((size_t)(b*Tt + t)*Nn)*Dd + h*HDm;
    for (int idx = threadIdx.x; idx < Nn*HDm; idx += 256) {
        int n = idx >> 4, d = idx & 15;
        Ys[n*17 + d] = qbase[(size_t)n*Dd + d];
    }
    __syncthreads();

    int warp = threadIdx.x >> 5, lane = threadIdx.x & 31;
    int rstart = blockIdx.x * 77;
    int rend = min(Nn, rstart + 77);
    float* Pb = g_P + (size_t)slice*SLICE_CP;

    for (int n = rstart + warp; n < rend; n += 8) {
        float qn[16];
        #pragma unroll
        for (int d = 0; d < 16; d++) qn[d] = Ys[n*17 + d];
        float e[10]; float mx = -1e30f;
        #pragma unroll
        for (int k = 0; k < 10; k++) {
            int m = lane + 32*k;
            float s = -1e30f;
            if (m < Nn) {
                float a = 0.f;
                #pragma unroll
                for (int d = 0; d < 16; d++) a += qn[d]*Ys[m*17 + d];
                s = fmaxf(a * 0.125f, 0.f);
            }
            e[k] = s; mx = fmaxf(mx, s);
        }
        #pragma unroll
        for (int o = 16; o; o >>= 1) mx = fmaxf(mx, __shfl_xor_sync(0xffffffffu, mx, o));
        float sum = 0.f;
        #pragma unroll
        for (int k = 0; k < 10; k++) { float v = __expf(e[k] - mx); e[k] = v; sum += v; }
        #pragma unroll
        for (int o = 16; o; o >>= 1) sum += __shfl_xor_sync(0xffffffffu, sum, o);
        float inv = 1.f / sum;
        #pragma unroll
        for (int k = 0; k < 10; k++) {
            int m = lane + 32*k;                    // covers 0..319 exactly
            Pb[(size_t)n*LDP + m] = e[k]*inv;       // pads (m>=307) get 0
        }
    }
}

// ---------------- kernel 5: dyn = P @ EgP via tf32 mma.sync ----------------
// block tile 128x64, BK=32; 8 warps in 4x2, warp tile 32x32 (2x4 m16n8k8)
#define MMA_TF32(d0,d1,d2,d3,a0,a1,a2,a3,b0,b1) \
    asm volatile("mma.sync.aligned.m16n8k8.row.col.f32.tf32.tf32.f32 " \
                 "{%0,%1,%2,%3},{%4,%5,%6,%7},{%8,%9},{%0,%1,%2,%3};" \
                 : "+f"(d0),"+f"(d1),"+f"(d2),"+f"(d3) \
                 : "r"(a0),"r"(a1),"r"(a2),"r"(a3),"r"(b0),"r"(b1))

__global__ __launch_bounds__(256) void dyn_gemm_tc() {
    int slice = blockIdx.z;
    const float* A = g_P + (size_t)slice*SLICE_CP;   // [384][320]
    float* C = g_dyn + (size_t)slice*SLICE_CP;       // [384][320]
    int rowBase = blockIdx.y * 128;                  // 0,128,256
    int colBase = blockIdx.x * 64;                   // 0..256

    __shared__ unsigned As[32][136];   // [k][m], stride%32==8 -> conflict-free frags
    __shared__ unsigned Bs[32][72];    // [k][n]

    int tid = threadIdx.x, lane = tid & 31, warp = tid >> 5;
    int wm = warp & 3, wn = warp >> 2;               // 4 row-warps x 2 col-warps
    int gid = lane >> 2, tig = lane & 3;

    float c[2][4][4] = {};

    int ar  = tid >> 1;            // 0..127, A row within tile
    int akq = (tid & 1) * 16;      // k chunk 0 or 16
    int bk0 = tid >> 4;            // 0..15, B k row (2 passes)
    int bnq = (tid & 15) * 4;      // B col quad

    const float* Ag = A + (size_t)(rowBase + ar)*LDP;

    for (int kt = 0; kt < LDP; kt += 32) {
        // load A tile 128x32, transpose into As[k][m] (tf32-rounded)
        #pragma unroll
        for (int q = 0; q < 4; q++) {
            float4 v = *(const float4*)(Ag + kt + akq + q*4);
            As[akq + q*4 + 0][ar] = f2tf(v.x);
            As[akq + q*4 + 1][ar] = f2tf(v.y);
            As[akq + q*4 + 2][ar] = f2tf(v.z);
            As[akq + q*4 + 3][ar] = f2tf(v.w);
        }
        // load B tile 32x64
        #pragma unroll
        for (int p = 0; p < 2; p++) {
            int kk = bk0 + p*16;
            float4 v = *(const float4*)(g_EgP + (size_t)(kt + kk)*LDP + colBase + bnq);
            uint4 u = make_uint4(f2tf(v.x), f2tf(v.y), f2tf(v.z), f2tf(v.w));
            *(uint4*)&Bs[kk][bnq] = u;
        }
        __syncthreads();

        #pragma unroll
        for (int kb = 0; kb < 32; kb += 8) {
            unsigned a[2][4], b[4][2];
            #pragma unroll
            for (int mi = 0; mi < 2; mi++) {
                int mb = wm*32 + mi*16;
                a[mi][0] = As[kb + tig    ][mb + gid    ];
                a[mi][1] = As[kb + tig    ][mb + gid + 8];
                a[mi][2] = As[kb + tig + 4][mb + gid    ];
                a[mi][3] = As[kb + tig + 4][mb + gid + 8];
            }
            #pragma unroll
            for (int ni = 0; ni < 4; ni++) {
                int nb = wn*32 + ni*8;
                b[ni][0] = Bs[kb + tig    ][nb + gid];
                b[ni][1] = Bs[kb + tig + 4][nb + gid];
            }
            #pragma unroll
            for (int mi = 0; mi < 2; mi++)
                #pragma unroll
                for (int ni = 0; ni < 4; ni++)
                    MMA_TF32(c[mi][ni][0], c[mi][ni][1], c[mi][ni][2], c[mi][ni][3],
                             a[mi][0], a[mi][1], a[mi][2], a[mi][3],
                             b[ni][0], b[ni][1]);
        }
        __syncthreads();
    }

    #pragma unroll
    for (int mi = 0; mi < 2; mi++) {
        int r0 = rowBase + wm*32 + mi*16 + gid;
        #pragma unroll
        for (int ni = 0; ni < 4; ni++) {
            int col = colBase + wn*32 + ni*8 + tig*2;
            *(float2*)&C[(size_t)r0*LDP + col]       = make_float2(c[mi][ni][0], c[mi][ni][1]);
            *(float2*)&C[(size_t)(r0 + 8)*LDP + col] = make_float2(c[mi][ni][2], c[mi][ni][3]);
        }
    }
}

// ---------------- kernel 6: attention + tanh + merge + combine ----------------
__global__ __launch_bounds__(256, 2) void attn_kernel(float* __restrict__ out) {
    int slice = blockIdx.y;
    int hb = slice / Tt, t = slice % Tt;
    int h = hb / Bb, b = hb % Bb;
    __shared__ float Ks[Nn*17];
    __shared__ float Vs[Nn*17];
    size_t sl_off = ((size_t)(b*Tt + t)*Nn)*Dd + h*HDm;
    const float* kbase = g_k2 + sl_off;
    const float* vbase = g_v2 + sl_off;
    const float* qbase = g_q2 + sl_off;
    for (int idx = threadIdx.x; idx < Nn*HDm; idx += 256) {
        int n = idx >> 4, d = idx & 15;
        Ks[n*17 + d] = kbase[(size_t)n*Dd + d];
        Vs[n*17 + d] = vbase[(size_t)n*Dd + d];
    }
    __syncthreads();

    int warp = threadIdx.x >> 5, lane = threadIdx.x & 31;
    int rstart = blockIdx.x * 77;
    int rend = min(Nn, rstart + 77);
    const float* dynb = g_dyn + (size_t)slice*SLICE_CP;

    for (int n = rstart + warp; n < rend; n += 8) {
        float qn[16];
        #pragma unroll
        for (int d = 0; d < 16; d++) qn[d] = qbase[(size_t)n*Dd + d];
        float e[10]; float mx = -1e30f;
        #pragma unroll
        for (int k = 0; k < 10; k++) {
            int m = lane + 32*k;
            float s = -1e30f;
            if (m < Nn) {
                float a = 0.f;
                #pragma unroll
                for (int d = 0; d < 16; d++) a += qn[d]*Ks[m*17 + d];
                s = (a * 0.25f) * dynb[(size_t)n*LDP + m];
            }
            e[k] = s; mx = fmaxf(mx, s);
        }
        #pragma unroll
        for (int o = 16; o; o >>= 1) mx = fmaxf(mx, __shfl_xor_sync(0xffffffffu, mx, o));
        float sum = 0.f;
        #pragma unroll
        for (int k = 0; k < 10; k++) { float v = __expf(e[k] - mx); e[k] = v; sum += v; }
        #pragma unroll
        for (int o = 16; o; o >>= 1) sum += __shfl_xor_sync(0xffffffffu, sum, o);
        float inv = 1.f / sum;

        float acc[16];
        #pragma unroll
        for (int d = 0; d < 16; d++) acc[d] = 0.f;
        #pragma unroll
        for (int k = 0; k < 10; k++) {
            int m = lane + 32*k;
            if (m < Nn) {
                float w = e[k]*inv;
                #pragma unroll
                for (int d = 0; d < 16; d++) acc[d] += w * Vs[m*17 + d];
            }
        }
        #pragma unroll
        for (int d = 0; d < 16; d++) {
            #pragma unroll
            for (int o = 16; o; o >>= 1) acc[d] += __shfl_xor_sync(0xffffffffu, acc[d], o);
        }
        if (lane < 16) {
            size_t oidx = ((size_t)(b*Tt + t)*Nn + n)*Dd + h*HDm + lane;
            out[oidx] = g_out1h[oidx] + 0.5f * tanhf(acc[lane]);
        }
    }
}

// ---------------- launch ----------------
extern "C" void kernel_launch(void* const* d_in, const int* in_sizes, int n_in,
                              void* d_out, int out_size) {
    const float* query  = (const float*)d_in[0];
    const float* key_in = (const float*)d_in[1];
    const float* value  = (const float*)d_in[2];
    const float* adj    = (const float*)d_in[3];
    const float* Eg     = (const float*)d_in[4];
    const float* Wq     = (const float*)d_in[5];
    const float* bq     = (const float*)d_in[6];
    const float* Wk     = (const float*)d_in[7];
    const float* bk     = (const float*)d_in[8];
    const float* Wv     = (const float*)d_in[9];
    const float* bv     = (const float*)d_in[10];
    const float* Wt     = (const float*)d_in[11];
    const float* bt     = (const float*)d_in[12];
    float* out = (float*)d_out;

    nadj_kernel<<<Nn, 256>>>(adj);
    egpack_kernel<<<LDP, 256>>>(Eg);
    linear_kernel<<<dim3((BTN + 63)/64, 1, 4), 256>>>(query, key_in, value,
                                                      Wq, bq, Wk, bk, Wv, bv, Wt);
    graphconv_kernel<<<dim3(5, Bb*Tt), 256>>>(bt);
    pmat_kernel<<<dim3(4, NSLICE), 256>>>(query);
    dyn_gemm_tc<<<dim3(5, 3, NSLICE), 256>>>();
    attn_kernel<<<dim3(4, NSLICE), 256>>>(out);
}

// round 4
// speedup vs baseline: 1.7385x; 1.1380x over previous
#include <cuda_runtime.h>
#include <math.h>

#define Bb 8
#define Tt 12
#define Nn 307
#define Dd 64
#define Hh 4
#define HDm 16
#define NSLICE (Hh*Bb*Tt)        /* 384 */
#define NN (Nn*Nn)               /* 94249 */
#define BTN (Bb*Tt*Nn)           /* 29472 */
#define BTND (BTN*Dd)            /* 1886208 */

#define LDP 320                  /* padded inner stride for P/dyn/EgP */
#define MR  384                  /* padded row count for P/dyn */
#define SLICE_CP (MR*LDP)        /* 122880 floats per slice */

// ---------------- scratch (static device globals; zero-init, no allocs) ----
__device__ float g_nadj[NN];
__device__ float g_q2[BTND];
__device__ float g_k2[BTND];
__device__ float g_v2[BTND];
__device__ float g_qt[BTND];
__device__ float g_out1h[BTND];                    // 0.5*relu(graphconv)
__device__ float g_P[(size_t)NSLICE*SLICE_CP];     // padded tf32 bits of softmax(relu(YY^T/8))
__device__ float g_dyn[(size_t)NSLICE*SLICE_CP];   // padded P @ E_g (f32)
__device__ float g_EgP[LDP*LDP];                   // padded tf32 bits of E_g

__device__ __forceinline__ unsigned f2tf(float f) {
    unsigned u;
    asm("cvt.rna.tf32.f32 %0, %1;" : "=r"(u) : "f"(f));
    return u;
}

// ---------------- kernel 1: normalized adjacency ----------------
__global__ void nadj_kernel(const float* __restrict__ adj) {
    int i = blockIdx.x;
    __shared__ float red[256];
    float s = 0.f;
    for (int j = threadIdx.x; j < Nn; j += 256) s += adj[i*Nn + j];
    red[threadIdx.x] = s; __syncthreads();
    for (int w = 128; w > 0; w >>= 1) {
        if (threadIdx.x < w) red[threadIdx.x] += red[threadIdx.x + w];
        __syncthreads();
    }
    float inv = 1.f / (red[0] + 1.f);   // +1 for the identity diagonal
    for (int j = threadIdx.x; j < Nn; j += 256) {
        float v = adj[i*Nn + j] + (j == i ? 1.f : 0.f);
        g_nadj[i*Nn + j] = v * inv;
    }
}

// ---------------- kernel 1b: pack E_g as tf32 bits into padded [320][320] ----
__global__ void egpack_kernel(const float* __restrict__ Eg) {
    int r = blockIdx.x;                // 0..319
    for (int c = threadIdx.x; c < LDP; c += 256) {
        float v = (r < Nn && c < Nn) ? Eg[r*Nn + c] : 0.f;
        g_EgP[r*LDP + c] = __uint_as_float(f2tf(v));
    }
}

// ---------------- kernel 2: batched linear X @ W^T (+ bias) ----------------
__global__ void linear_kernel(const float* __restrict__ query,
                              const float* __restrict__ key_in,
                              const float* __restrict__ value,
                              const float* __restrict__ Wq, const float* __restrict__ bq,
                              const float* __restrict__ Wk, const float* __restrict__ bk,
                              const float* __restrict__ Wv, const float* __restrict__ bv,
                              const float* __restrict__ Wt) {
    int which = blockIdx.z;
    const float* X; const float* W; const float* bias; float* out;
    if (which == 0)      { X = query;  W = Wq; bias = bq;      out = g_q2; }
    else if (which == 1) { X = key_in; W = Wk; bias = bk;      out = g_k2; }
    else if (which == 2) { X = value;  W = Wv; bias = bv;      out = g_v2; }
    else                 { X = query;  W = Wt; bias = nullptr; out = g_qt; }

    __shared__ float Xs[64][65];
    __shared__ float Wts[64][65];
    int tid = threadIdx.x;
    int rowBase = blockIdx.x * 64;
    int rows = min(64, BTN - rowBase);

    for (int idx = tid; idx < 64*64; idx += 256) {
        int r = idx >> 6, c = idx & 63;
        Xs[r][c] = (r < rows) ? X[(size_t)(rowBase + r)*64 + c] : 0.f;
    }
    for (int idx = tid; idx < 64*64; idx += 256) {
        int j = idx >> 6, k = idx & 63;
        Wts[k][j] = W[idx];
    }
    __syncthreads();

    int ty = tid >> 4, tx = tid & 15;
    int r0 = ty*4, c0 = tx*4;
    float acc[4][4] = {};
    for (int k = 0; k < 64; k++) {
        float a[4], b4[4];
        #pragma unroll
        for (int i = 0; i < 4; i++) a[i] = Xs[r0 + i][k];
        #pragma unroll
        for (int j = 0; j < 4; j++) b4[j] = Wts[k][c0 + j];
        #pragma unroll
        for (int i = 0; i < 4; i++)
            #pragma unroll
            for (int j = 0; j < 4; j++) acc[i][j] += a[i]*b4[j];
    }
    #pragma unroll
    for (int i = 0; i < 4; i++) {
        int r = r0 + i;
        if (r < rows) {
            #pragma unroll
            for (int j = 0; j < 4; j++) {
                float v = acc[i][j];
                if (bias) v += bias[c0 + j];
                out[(size_t)(rowBase + r)*64 + c0 + j] = v;
            }
        }
    }
}

// ---------------- kernel 3: graph conv: 0.5*relu(nadj @ qt + bt) ----------------
__global__ void graphconv_kernel(const float* __restrict__ bt_bias) {
    int bt = blockIdx.y;
    int rowBase = blockIdx.x * 64;
    const float* Bm = g_qt + (size_t)bt*Nn*Dd;
    float* out = g_out1h + (size_t)bt*Nn*Dd;

    __shared__ float As[16][68];
    __shared__ float Bs[16][68];
    int tid = threadIdx.x;
    int ty = tid >> 4, tx = tid & 15;
    int r0 = ty*4, c0 = tx*4;
    float acc[4][4] = {};

    for (int kt = 0; kt < Nn; kt += 16) {
        for (int idx = tid; idx < 64*16; idx += 256) {
            int kk = idx & 15, m = idx >> 4;
            int gr = rowBase + m, gk = kt + kk;
            As[kk][m] = (gr < Nn && gk < Nn) ? g_nadj[(size_t)gr*Nn + gk] : 0.f;
        }
        for (int idx = tid; idx < 64*16; idx += 256) {
            int n = idx & 63, kk = idx >> 6;
            int gk = kt + kk;
            Bs[kk][n] = (gk < Nn) ? Bm[(size_t)gk*64 + n] : 0.f;
        }
        __syncthreads();
        #pragma unroll
        for (int k = 0; k < 16; k++) {
            float4 av = *(const float4*)&As[k][r0];
            float4 bv = *(const float4*)&Bs[k][c0];
            float a[4] = {av.x, av.y, av.z, av.w};
            float b4[4] = {bv.x, bv.y, bv.z, bv.w};
            #pragma unroll
            for (int i = 0; i < 4; i++)
                #pragma unroll
                for (int j = 0; j < 4; j++) acc[i][j] += a[i]*b4[j];
        }
        __syncthreads();
    }
    #pragma unroll
    for (int i = 0; i < 4; i++) {
        int r = rowBase + r0 + i;
        if (r < Nn) {
            #pragma unroll
            for (int j = 0; j < 4; j++) {
                int c = c0 + j;
                float v = acc[i][j] + bt_bias[c];
                out[(size_t)r*64 + c] = 0.5f * fmaxf(v, 0.f);
            }
        }
    }
}

// ---------------- kernel 4: P = softmax(relu(Y Y^T / 8)), stored as tf32 bits ----
__global__ __launch_bounds__(256, 2) void pmat_kernel(const float* __restrict__ query) {
    int slice = blockIdx.y;
    int hb = slice / Tt, t = slice % Tt;
    int h = hb / Bb, b = hb % Bb;
    __shared__ float Ys[Nn*17];
    const float* qbase = query + ((size_t)(b*Tt + t)*Nn)*Dd + h*HDm;
    for (int idx = threadIdx.x; idx < Nn*HDm; idx += 256) {
        int n = idx >> 4, d = idx & 15;
        Ys[n*17 + d] = qbase[(size_t)n*Dd + d];
    }
    __syncthreads();

    int warp = threadIdx.x >> 5, lane = threadIdx.x & 31;
    int rstart = blockIdx.x * 77;
    int rend = min(Nn, rstart + 77);
    float* Pb = g_P + (size_t)slice*SLICE_CP;

    for (int n = rstart + warp; n < rend; n += 8) {
        float qn[16];
        #pragma unroll
        for (int d = 0; d < 16; d++) qn[d] = Ys[n*17 + d];
        float e[10]; float mx = -1e30f;
        #pragma unroll
        for (int k = 0; k < 10; k++) {
            int m = lane + 32*k;
            float s = -1e30f;
            if (m < Nn) {
                float a = 0.f;
                #pragma unroll
                for (int d = 0; d < 16; d++) a += qn[d]*Ys[m*17 + d];
                s = fmaxf(a * 0.125f, 0.f);
            }
            e[k] = s; mx = fmaxf(mx, s);
        }
        #pragma unroll
        for (int o = 16; o; o >>= 1) mx = fmaxf(mx, __shfl_xor_sync(0xffffffffu, mx, o));
        float sum = 0.f;
        #pragma unroll
        for (int k = 0; k < 10; k++) { float v = __expf(e[k] - mx); e[k] = v; sum += v; }
        #pragma unroll
        for (int o = 16; o; o >>= 1) sum += __shfl_xor_sync(0xffffffffu, sum, o);
        float inv = 1.f / sum;
        #pragma unroll
        for (int k = 0; k < 10; k++) {
            int m = lane + 32*k;                                   // covers 0..319
            Pb[(size_t)n*LDP + m] = __uint_as_float(f2tf(e[k]*inv)); // pads get 0
        }
    }
}

// ---------------- kernel 5: dyn = P @ EgP, tf32 mma + cp.async double buffer ----
// block tile 128x64, BK=32, 2 stages; 8 warps 4x2; warp tile 32x32 (2x4 m16n8k8)
#define BMt 128
#define BNt 64
#define BKt 32
#define ASTR 36
#define BSTR 72
#define STAGE_A (BMt*ASTR)            /* 4608 words */
#define STAGE_B (BKt*BSTR)            /* 2304 words */
#define DYN_SMEM_BYTES ((2*STAGE_A + 2*STAGE_B)*4)   /* 55296 */

#define MMA_TF32(d0,d1,d2,d3,a0,a1,a2,a3,b0,b1) \
    asm volatile("mma.sync.aligned.m16n8k8.row.col.f32.tf32.tf32.f32 " \
                 "{%0,%1,%2,%3},{%4,%5,%6,%7},{%8,%9},{%0,%1,%2,%3};" \
                 : "+f"(d0),"+f"(d1),"+f"(d2),"+f"(d3) \
                 : "r"(a0),"r"(a1),"r"(a2),"r"(a3),"r"(b0),"r"(b1))

#define CP_ASYNC16(dst_u32, src_ptr) \
    asm volatile("cp.async.cg.shared.global [%0], [%1], 16;" :: "r"(dst_u32), "l"(src_ptr))

__global__ __launch_bounds__(256) void dyn_gemm_tc() {
    extern __shared__ unsigned dsm[];
    unsigned* AsBase = dsm;                 // [2][BMt][ASTR]
    unsigned* BsBase = dsm + 2*STAGE_A;     // [2][BKt][BSTR]

    int slice = blockIdx.z;
    const float* A = g_P + (size_t)slice*SLICE_CP;   // [384][320] tf32 bits
    float* C = g_dyn + (size_t)slice*SLICE_CP;
    int rowBase = blockIdx.y * BMt;                  // 0,128,256
    int colBase = blockIdx.x * BNt;                  // 0..256

    int tid = threadIdx.x, lane = tid & 31, warp = tid >> 5;
    int wm = warp & 3, wn = warp >> 2;
    int gid = lane >> 2, tig = lane & 3;

    // load assignments
    int am  = tid >> 3;            // 0..31 (A row group base)
    int akq = (tid & 7) * 4;       // A k quad
    int bk  = tid >> 4;            // 0..15 (B k row)
    int bnq = (tid & 15) * 4;      // B col quad

    unsigned aSm = (unsigned)__cvta_generic_to_shared(AsBase);
    unsigned bSm = (unsigned)__cvta_generic_to_shared(BsBase);

    float c[2][4][4] = {};

    auto load_tiles = [&](int kt, int s) {
        unsigned aDst = aSm + (unsigned)(s*STAGE_A)*4u;
        #pragma unroll
        for (int j = 0; j < 4; j++) {
            int row = am + 32*j;
            CP_ASYNC16(aDst + (unsigned)(row*ASTR + akq)*4u,
                       A + (size_t)(rowBase + row)*LDP + kt + akq);
        }
        unsigned bDst = bSm + (unsigned)(s*STAGE_B)*4u;
        #pragma unroll
        for (int j = 0; j < 2; j++) {
            int kk = bk + 16*j;
            CP_ASYNC16(bDst + (unsigned)(kk*BSTR + bnq)*4u,
                       g_EgP + (size_t)(kt + kk)*LDP + colBase + bnq);
        }
    };

    load_tiles(0, 0);
    asm volatile("cp.async.commit_group;");

    const int NT = LDP / BKt;   // 10
    for (int it = 0; it < NT; it++) {
        if (it < NT - 1) {
            load_tiles((it + 1)*BKt, (it + 1) & 1);
            asm volatile("cp.async.commit_group;");
            asm volatile("cp.async.wait_group 1;");
        } else {
            asm volatile("cp.async.wait_group 0;");
        }
        __syncthreads();

        const unsigned* As = AsBase + (it & 1)*STAGE_A;   // [m][ASTR]
        const unsigned* Bs = BsBase + (it & 1)*STAGE_B;   // [k][BSTR]

        #pragma unroll
        for (int kb = 0; kb < BKt; kb += 8) {
            unsigned a[2][4], b[4][2];
            #pragma unroll
            for (int mi = 0; mi < 2; mi++) {
                int mb = wm*32 + mi*16;
                a[mi][0] = As[(mb + gid    )*ASTR + kb + tig    ];
                a[mi][1] = As[(mb + gid + 8)*ASTR + kb + tig    ];
                a[mi][2] = As[(mb + gid    )*ASTR + kb + tig + 4];
                a[mi][3] = As[(mb + gid + 8)*ASTR + kb + tig + 4];
            }
            #pragma unroll
            for (int ni = 0; ni < 4; ni++) {
                int nb = wn*32 + ni*8;
                b[ni][0] = Bs[(kb + tig    )*BSTR + nb + gid];
                b[ni][1] = Bs[(kb + tig + 4)*BSTR + nb + gid];
            }
            #pragma unroll
            for (int mi = 0; mi < 2; mi++)
                #pragma unroll
                for (int ni = 0; ni < 4; ni++)
                    MMA_TF32(c[mi][ni][0], c[mi][ni][1], c[mi][ni][2], c[mi][ni][3],
                             a[mi][0], a[mi][1], a[mi][2], a[mi][3],
                             b[ni][0], b[ni][1]);
        }
        __syncthreads();
    }

    #pragma unroll
    for (int mi = 0; mi < 2; mi++) {
        int r0 = rowBase + wm*32 + mi*16 + gid;
        #pragma unroll
        for (int ni = 0; ni < 4; ni++) {
            int col = colBase + wn*32 + ni*8 + tig*2;
            *(float2*)&C[(size_t)r0*LDP + col]       = make_float2(c[mi][ni][0], c[mi][ni][1]);
            *(float2*)&C[(size_t)(r0 + 8)*LDP + col] = make_float2(c[mi][ni][2], c[mi][ni][3]);
        }
    }
}

// ---------------- kernel 6: attention + tanh + merge + combine ----------------
__global__ __launch_bounds__(256, 2) void attn_kernel(float* __restrict__ out) {
    int slice = blockIdx.y;
    int hb = slice / Tt, t = slice % Tt;
    int h = hb / Bb, b = hb % Bb;
    __shared__ float Ks[Nn*17];
    __shared__ float Vs[Nn*17];
    size_t sl_off = ((size_t)(b*Tt + t)*Nn)*Dd + h*HDm;
    const float* kbase = g_k2 + sl_off;
    const float* vbase = g_v2 + sl_off;
    const float* qbase = g_q2 + sl_off;
    for (int idx = threadIdx.x; idx < Nn*HDm; idx += 256) {
        int n = idx >> 4, d = idx & 15;
        Ks[n*17 + d] = kbase[(size_t)n*Dd + d];
        Vs[n*17 + d] = vbase[(size_t)n*Dd + d];
    }
    __syncthreads();

    int warp = threadIdx.x >> 5, lane = threadIdx.x & 31;
    int rstart = blockIdx.x * 77;
    int rend = min(Nn, rstart + 77);
    const float* dynb = g_dyn + (size_t)slice*SLICE_CP;

    for (int n = rstart + warp; n < rend; n += 8) {
        float qn[16];
        #pragma unroll
        for (int d = 0; d < 16; d++) qn[d] = qbase[(size_t)n*Dd + d];
        float e[10]; float mx = -1e30f;
        #pragma unroll
        for (int k = 0; k < 10; k++) {
            int m = lane + 32*k;
            float s = -1e30f;
            if (m < Nn) {
                float a = 0.f;
                #pragma unroll
                for (int d = 0; d < 16; d++) a += qn[d]*Ks[m*17 + d];
                s = (a * 0.25f) * dynb[(size_t)n*LDP + m];
            }
            e[k] = s; mx = fmaxf(mx, s);
        }
        #pragma unroll
        for (int o = 16; o; o >>= 1) mx = fmaxf(mx, __shfl_xor_sync(0xffffffffu, mx, o));
        float sum = 0.f;
        #pragma unroll
        for (int k = 0; k < 10; k++) { float v = __expf(e[k] - mx); e[k] = v; sum += v; }
        #pragma unroll
        for (int o = 16; o; o >>= 1) sum += __shfl_xor_sync(0xffffffffu, sum, o);
        float inv = 1.f / sum;

        float acc[16];
        #pragma unroll
        for (int d = 0; d < 16; d++) acc[d] = 0.f;
        #pragma unroll
        for (int k = 0; k < 10; k++) {
            int m = lane + 32*k;
            if (m < Nn) {
                float w = e[k]*inv;
                #pragma unroll
                for (int d = 0; d < 16; d++) acc[d] += w * Vs[m*17 + d];
            }
        }
        #pragma unroll
        for (int d = 0; d < 16; d++) {
            #pragma unroll
            for (int o = 16; o; o >>= 1) acc[d] += __shfl_xor_sync(0xffffffffu, acc[d], o);
        }
        if (lane < 16) {
            size_t oidx = ((size_t)(b*Tt + t)*Nn + n)*Dd + h*HDm + lane;
            out[oidx] = g_out1h[oidx] + 0.5f * tanhf(acc[lane]);
        }
    }
}

// ---------------- launch ----------------
extern "C" void kernel_launch(void* const* d_in, const int* in_sizes, int n_in,
                              void* d_out, int out_size) {
    const float* query  = (const float*)d_in[0];
    const float* key_in = (const float*)d_in[1];
    const float* value  = (const float*)d_in[2];
    const float* adj    = (const float*)d_in[3];
    const float* Eg     = (const float*)d_in[4];
    const float* Wq     = (const float*)d_in[5];
    const float* bq     = (const float*)d_in[6];
    const float* Wk     = (const float*)d_in[7];
    const float* bk     = (const float*)d_in[8];
    const float* Wv     = (const float*)d_in[9];
    const float* bv     = (const float*)d_in[10];
    const float* Wt     = (const float*)d_in[11];
    const float* bt     = (const float*)d_in[12];
    float* out = (float*)d_out;

    cudaFuncSetAttribute(dyn_gemm_tc,
                         cudaFuncAttributeMaxDynamicSharedMemorySize, DYN_SMEM_BYTES);

    nadj_kernel<<<Nn, 256>>>(adj);
    egpack_kernel<<<LDP, 256>>>(Eg);
    linear_kernel<<<dim3((BTN + 63)/64, 1, 4), 256>>>(query, key_in, value,
                                                      Wq, bq, Wk, bk, Wv, bv, Wt);
    graphconv_kernel<<<dim3(5, Bb*Tt), 256>>>(bt);
    pmat_kernel<<<dim3(4, NSLICE), 256>>>(query);
    dyn_gemm_tc<<<dim3(5, 3, NSLICE), 256, DYN_SMEM_BYTES>>>();
    attn_kernel<<<dim3(4, NSLICE), 256>>>(out);
}

// round 5
// speedup vs baseline: 2.0547x; 1.1819x over previous
#include <cuda_runtime.h>
#include <math.h>

#define Bb 8
#define Tt 12
#define Nn 307
#define Dd 64
#define Hh 4
#define HDm 16
#define NSLICE (Hh*Bb*Tt)        /* 384 */
#define NN (Nn*Nn)               /* 94249 */
#define BTN (Bb*Tt*Nn)           /* 29472 */
#define BTND (BTN*Dd)            /* 1886208 */

#define LDP 320                  /* padded inner stride for P/dyn/EgP/nadjP */
#define MR  384                  /* padded row count */
#define SLICE_CP (MR*LDP)        /* 122880 floats per slice */

// ---------------- scratch (static device globals; zero-init, no allocs) ----
__device__ float g_nadjP[MR*LDP];                  // padded tf32 bits of nadj [384][320]
__device__ float g_q2[BTND];
__device__ float g_k2[BTND];
__device__ float g_v2[BTND];
__device__ float g_qtP[Bb*Tt*LDP*Dd];              // padded tf32 bits of q@Wt^T [96][320][64]
__device__ float g_out1h[BTND];                    // 0.5*relu(graphconv)
__device__ float g_P[(size_t)NSLICE*SLICE_CP];     // padded tf32 bits of softmax(relu(YY^T/8))
__device__ float g_dyn[(size_t)NSLICE*SLICE_CP];   // padded P @ E_g (f32)
__device__ float g_EgP[LDP*LDP];                   // padded tf32 bits of E_g

__device__ __forceinline__ unsigned f2tf(float f) {
    unsigned u;
    asm("cvt.rna.tf32.f32 %0, %1;" : "=r"(u) : "f"(f));
    return u;
}

// ---------------- shared GEMM plumbing (tf32 mma + cp.async, 128x64xK) -----
#define BMt 128
#define BNt 64
#define BKt 32
#define ASTR 36
#define BSTR 72
#define STAGE_A (BMt*ASTR)            /* 4608 words */
#define STAGE_B (BKt*BSTR)            /* 2304 words */
#define GEMM_SMEM_BYTES ((2*STAGE_A + 2*STAGE_B)*4)   /* 55296 */

#define MMA_TF32(d0,d1,d2,d3,a0,a1,a2,a3,b0,b1) \
    asm volatile("mma.sync.aligned.m16n8k8.row.col.f32.tf32.tf32.f32 " \
                 "{%0,%1,%2,%3},{%4,%5,%6,%7},{%8,%9},{%0,%1,%2,%3};" \
                 : "+f"(d0),"+f"(d1),"+f"(d2),"+f"(d3) \
                 : "r"(a0),"r"(a1),"r"(a2),"r"(a3),"r"(b0),"r"(b1))

#define CP_ASYNC16(dst_u32, src_ptr) \
    asm volatile("cp.async.cg.shared.global [%0], [%1], 16;" :: "r"(dst_u32), "l"(src_ptr))

// ---------------- kernel 1: normalized adjacency -> padded tf32 -----------
__global__ void nadj_kernel(const float* __restrict__ adj) {
    int i = blockIdx.x;
    __shared__ float red[256];
    float s = 0.f;
    for (int j = threadIdx.x; j < Nn; j += 256) s += adj[i*Nn + j];
    red[threadIdx.x] = s; __syncthreads();
    for (int w = 128; w > 0; w >>= 1) {
        if (threadIdx.x < w) red[threadIdx.x] += red[threadIdx.x + w];
        __syncthreads();
    }
    float inv = 1.f / (red[0] + 1.f);   // +1 for the identity diagonal
    for (int j = threadIdx.x; j < Nn; j += 256) {
        float v = (adj[i*Nn + j] + (j == i ? 1.f : 0.f)) * inv;
        g_nadjP[i*LDP + j] = __uint_as_float(f2tf(v));   // pads stay 0 (zero-init)
    }
}

// ---------------- kernel 1b: pack E_g as tf32 bits into padded [320][320] ----
__global__ void egpack_kernel(const float* __restrict__ Eg) {
    int r = blockIdx.x;                // 0..319
    for (int c = threadIdx.x; c < LDP; c += 256) {
        float v = (r < Nn && c < Nn) ? Eg[r*Nn + c] : 0.f;
        g_EgP[r*LDP + c] = __uint_as_float(f2tf(v));
    }
}

// ---------------- kernel 2: batched linear X @ W^T (+ bias) ----------------
__global__ void linear_kernel(const float* __restrict__ query,
                              const float* __restrict__ key_in,
                              const float* __restrict__ value,
                              const float* __restrict__ Wq, const float* __restrict__ bq,
                              const float* __restrict__ Wk, const float* __restrict__ bk,
                              const float* __restrict__ Wv, const float* __restrict__ bv,
                              const float* __restrict__ Wt) {
    int which = blockIdx.z;
    const float* X; const float* W; const float* bias; float* out;
    if (which == 0)      { X = query;  W = Wq; bias = bq;      out = g_q2; }
    else if (which == 1) { X = key_in; W = Wk; bias = bk;      out = g_k2; }
    else if (which == 2) { X = value;  W = Wv; bias = bv;      out = g_v2; }
    else                 { X = query;  W = Wt; bias = nullptr; out = g_qtP; }

    __shared__ float Xs[64][65];
    __shared__ float Wts[64][65];
    int tid = threadIdx.x;
    int rowBase = blockIdx.x * 64;
    int rows = min(64, BTN - rowBase);

    for (int idx = tid; idx < 64*64; idx += 256) {
        int r = idx >> 6, c = idx & 63;
        Xs[r][c] = (r < rows) ? X[(size_t)(rowBase + r)*64 + c] : 0.f;
    }
    for (int idx = tid; idx < 64*64; idx += 256) {
        int j = idx >> 6, k = idx & 63;
        Wts[k][j] = W[idx];
    }
    __syncthreads();

    int ty = tid >> 4, tx = tid & 15;
    int r0 = ty*4, c0 = tx*4;
    float acc[4][4] = {};
    for (int k = 0; k < 64; k++) {
        float a[4], b4[4];
        #pragma unroll
        for (int i = 0; i < 4; i++) a[i] = Xs[r0 + i][k];
        #pragma unroll
        for (int j = 0; j < 4; j++) b4[j] = Wts[k][c0 + j];
        #pragma unroll
        for (int i = 0; i < 4; i++)
            #pragma unroll
            for (int j = 0; j < 4; j++) acc[i][j] += a[i]*b4[j];
    }
    #pragma unroll
    for (int i = 0; i < 4; i++) {
        int r = r0 + i;
        if (r < rows) {
            int gr = rowBase + r;
            if (which == 3) {
                int bt = gr / Nn, n = gr % Nn;     // padded tf32 store for graphconv B
                size_t base = ((size_t)bt*LDP + n)*Dd;
                #pragma unroll
                for (int j = 0; j < 4; j++)
                    g_qtP[base + c0 + j] = __uint_as_float(f2tf(acc[i][j]));
            } else {
                #pragma unroll
                for (int j = 0; j < 4; j++)
                    out[(size_t)gr*64 + c0 + j] = acc[i][j] + bias[c0 + j];
            }
        }
    }
}

// ---------------- kernel 3: graph conv 0.5*relu(nadj@qt + bt) via tf32 mma ----
// grid (96 bt, 3 rowtiles); same pipeline as dyn GEMM, colBase=0, K=320
__global__ __launch_bounds__(256) void graphconv_tc(const float* __restrict__ btb) {
    extern __shared__ unsigned dsm[];
    unsigned* AsBase = dsm;
    unsigned* BsBase = dsm + 2*STAGE_A;

    int bt = blockIdx.x;
    int rowBase = blockIdx.y * BMt;                 // 0,128,256 (rows to 383, pads 0)
    const float* Bsrc = g_qtP + (size_t)bt*LDP*Dd;  // [320][64] tf32 bits
    float* out = g_out1h + (size_t)bt*Nn*Dd;

    int tid = threadIdx.x, lane = tid & 31, warp = tid >> 5;
    int wm = warp & 3, wn = warp >> 2;
    int gid = lane >> 2, tig = lane & 3;

    int am  = tid >> 3;            // A row group base
    int akq = (tid & 7) * 4;
    int bk  = tid >> 4;
    int bnq = (tid & 15) * 4;

    unsigned aSm = (unsigned)__cvta_generic_to_shared(AsBase);
    unsigned bSm = (unsigned)__cvta_generic_to_shared(BsBase);

    float c[2][4][4] = {};

    auto load_tiles = [&](int kt, int s) {
        unsigned aDst = aSm + (unsigned)(s*STAGE_A)*4u;
        #pragma unroll
        for (int j = 0; j < 4; j++) {
            int row = am + 32*j;
            CP_ASYNC16(aDst + (unsigned)(row*ASTR + akq)*4u,
                       g_nadjP + (size_t)(rowBase + row)*LDP + kt + akq);
        }
        unsigned bDst = bSm + (unsigned)(s*STAGE_B)*4u;
        #pragma unroll
        for (int j = 0; j < 2; j++) {
            int kk = bk + 16*j;
            CP_ASYNC16(bDst + (unsigned)(kk*BSTR + bnq)*4u,
                       Bsrc + (size_t)(kt + kk)*Dd + bnq);
        }
    };

    load_tiles(0, 0);
    asm volatile("cp.async.commit_group;");

    const int NT = LDP / BKt;   // 10
    for (int it = 0; it < NT; it++) {
        if (it < NT - 1) {
            load_tiles((it + 1)*BKt, (it + 1) & 1);
            asm volatile("cp.async.commit_group;");
            asm volatile("cp.async.wait_group 1;");
        } else {
            asm volatile("cp.async.wait_group 0;");
        }
        __syncthreads();

        const unsigned* As = AsBase + (it & 1)*STAGE_A;
        const unsigned* Bs = BsBase + (it & 1)*STAGE_B;

        #pragma unroll
        for (int kb = 0; kb < BKt; kb += 8) {
            unsigned a[2][4], b[4][2];
            #pragma unroll
            for (int mi = 0; mi < 2; mi++) {
                int mb = wm*32 + mi*16;
                a[mi][0] = As[(mb + gid    )*ASTR + kb + tig    ];
                a[mi][1] = As[(mb + gid + 8)*ASTR + kb + tig    ];
                a[mi][2] = As[(mb + gid    )*ASTR + kb + tig + 4];
                a[mi][3] = As[(mb + gid + 8)*ASTR + kb + tig + 4];
            }
            #pragma unroll
            for (int ni = 0; ni < 4; ni++) {
                int nb = wn*32 + ni*8;
                b[ni][0] = Bs[(kb + tig    )*BSTR + nb + gid];
                b[ni][1] = Bs[(kb + tig + 4)*BSTR + nb + gid];
            }
            #pragma unroll
            for (int mi = 0; mi < 2; mi++)
                #pragma unroll
                for (int ni = 0; ni < 4; ni++)
                    MMA_TF32(c[mi][ni][0], c[mi][ni][1], c[mi][ni][2], c[mi][ni][3],
                             a[mi][0], a[mi][1], a[mi][2], a[mi][3],
                             b[ni][0], b[ni][1]);
        }
        __syncthreads();
    }

    #pragma unroll
    for (int mi = 0; mi < 2; mi++) {
        int r0 = rowBase + wm*32 + mi*16 + gid;
        #pragma unroll
        for (int ni = 0; ni < 4; ni++) {
            int col = wn*32 + ni*8 + tig*2;
            float b0 = btb[col], b1 = btb[col + 1];
            if (r0 < Nn)
                *(float2*)&out[(size_t)r0*Dd + col] = make_float2(
                    0.5f*fmaxf(c[mi][ni][0] + b0, 0.f), 0.5f*fmaxf(c[mi][ni][1] + b1, 0.f));
            if (r0 + 8 < Nn)
                *(float2*)&out[(size_t)(r0 + 8)*Dd + col] = make_float2(
                    0.5f*fmaxf(c[mi][ni][2] + b0, 0.f), 0.5f*fmaxf(c[mi][ni][3] + b1, 0.f));
        }
    }
}

// ---------------- kernel 4: P = softmax(relu(Y Y^T / 8)), tf32 bits, float4 smem
__global__ __launch_bounds__(256, 2) void pmat_kernel(const float* __restrict__ query) {
    int slice = blockIdx.y;
    int hb = slice / Tt, t = slice % Tt;
    int h = hb / Bb, b = hb % Bb;
    __shared__ float4 Ys4[Nn*5];                 // stride 5 float4 = 20 words, conflict-free
    const float* qbase = query + ((size_t)(b*Tt + t)*Nn)*Dd + h*HDm;
    for (int idx = threadIdx.x; idx < Nn*4; idx += 256) {
        int n = idx >> 2, q = idx & 3;
        Ys4[n*5 + q] = *(const float4*)(qbase + (size_t)n*Dd + q*4);
    }
    __syncthreads();

    int warp = threadIdx.x >> 5, lane = threadIdx.x & 31;
    int rstart = blockIdx.x * 77;
    int rend = min(Nn, rstart + 77);
    float* Pb = g_P + (size_t)slice*SLICE_CP;

    for (int n = rstart + warp; n < rend; n += 8) {
        float4 qn[4];
        #pragma unroll
        for (int q = 0; q < 4; q++) qn[q] = Ys4[n*5 + q];
        float e[10]; float mx = -1e30f;
        #pragma unroll
        for (int k = 0; k < 10; k++) {
            int m = lane + 32*k;
            float s = -1e30f;
            if (m < Nn) {
                float a = 0.f;
                #pragma unroll
                for (int q = 0; q < 4; q++) {
                    float4 km = Ys4[m*5 + q];
                    a += qn[q].x*km.x + qn[q].y*km.y + qn[q].z*km.z + qn[q].w*km.w;
                }
                s = fmaxf(a * 0.125f, 0.f);
            }
            e[k] = s; mx = fmaxf(mx, s);
        }
        #pragma unroll
        for (int o = 16; o; o >>= 1) mx = fmaxf(mx, __shfl_xor_sync(0xffffffffu, mx, o));
        float sum = 0.f;
        #pragma unroll
        for (int k = 0; k < 10; k++) { float v = __expf(e[k] - mx); e[k] = v; sum += v; }
        #pragma unroll
        for (int o = 16; o; o >>= 1) sum += __shfl_xor_sync(0xffffffffu, sum, o);
        float inv = 1.f / sum;
        #pragma unroll
        for (int k = 0; k < 10; k++) {
            int m = lane + 32*k;
            Pb[(size_t)n*LDP + m] = __uint_as_float(f2tf(e[k]*inv)); // pads get 0
        }
    }
}

// ---------------- kernel 5: dyn = P @ EgP, tf32 mma + cp.async double buffer ----
__global__ __launch_bounds__(256) void dyn_gemm_tc() {
    extern __shared__ unsigned dsm[];
    unsigned* AsBase = dsm;
    unsigned* BsBase = dsm + 2*STAGE_A;

    int slice = blockIdx.z;
    const float* A = g_P + (size_t)slice*SLICE_CP;
    float* C = g_dyn + (size_t)slice*SLICE_CP;
    int rowBase = blockIdx.y * BMt;
    int colBase = blockIdx.x * BNt;

    int tid = threadIdx.x, lane = tid & 31, warp = tid >> 5;
    int wm = warp & 3, wn = warp >> 2;
    int gid = lane >> 2, tig = lane & 3;

    int am  = tid >> 3;
    int akq = (tid & 7) * 4;
    int bk  = tid >> 4;
    int bnq = (tid & 15) * 4;

    unsigned aSm = (unsigned)__cvta_generic_to_shared(AsBase);
    unsigned bSm = (unsigned)__cvta_generic_to_shared(BsBase);

    float c[2][4][4] = {};

    auto load_tiles = [&](int kt, int s) {
        unsigned aDst = aSm + (unsigned)(s*STAGE_A)*4u;
        #pragma unroll
        for (int j = 0; j < 4; j++) {
            int row = am + 32*j;
            CP_ASYNC16(aDst + (unsigned)(row*ASTR + akq)*4u,
                       A + (size_t)(rowBase + row)*LDP + kt + akq);
        }
        unsigned bDst = bSm + (unsigned)(s*STAGE_B)*4u;
        #pragma unroll
        for (int j = 0; j < 2; j++) {
            int kk = bk + 16*j;
            CP_ASYNC16(bDst + (unsigned)(kk*BSTR + bnq)*4u,
                       g_EgP + (size_t)(kt + kk)*LDP + colBase + bnq);
        }
    };

    load_tiles(0, 0);
    asm volatile("cp.async.commit_group;");

    const int NT = LDP / BKt;   // 10
    for (int it = 0; it < NT; it++) {
        if (it < NT - 1) {
            load_tiles((it + 1)*BKt, (it + 1) & 1);
            asm volatile("cp.async.commit_group;");
            asm volatile("cp.async.wait_group 1;");
        } else {
            asm volatile("cp.async.wait_group 0;");
        }
        __syncthreads();

        const unsigned* As = AsBase + (it & 1)*STAGE_A;
        const unsigned* Bs = BsBase + (it & 1)*STAGE_B;

        #pragma unroll
        for (int kb = 0; kb < BKt; kb += 8) {
            unsigned a[2][4], b[4][2];
            #pragma unroll
            for (int mi = 0; mi < 2; mi++) {
                int mb = wm*32 + mi*16;
                a[mi][0] = As[(mb + gid    )*ASTR + kb + tig    ];
                a[mi][1] = As[(mb + gid + 8)*ASTR + kb + tig    ];
                a[mi][2] = As[(mb + gid    )*ASTR + kb + tig + 4];
                a[mi][3] = As[(mb + gid + 8)*ASTR + kb + tig + 4];
            }
            #pragma unroll
            for (int ni = 0; ni < 4; ni++) {
                int nb = wn*32 + ni*8;
                b[ni][0] = Bs[(kb + tig    )*BSTR + nb + gid];
                b[ni][1] = Bs[(kb + tig + 4)*BSTR + nb + gid];
            }
            #pragma unroll
            for (int mi = 0; mi < 2; mi++)
                #pragma unroll
                for (int ni = 0; ni < 4; ni++)
                    MMA_TF32(c[mi][ni][0], c[mi][ni][1], c[mi][ni][2], c[mi][ni][3],
                             a[mi][0], a[mi][1], a[mi][2], a[mi][3],
                             b[ni][0], b[ni][1]);
        }
        __syncthreads();
    }

    #pragma unroll
    for (int mi = 0; mi < 2; mi++) {
        int r0 = rowBase + wm*32 + mi*16 + gid;
        #pragma unroll
        for (int ni = 0; ni < 4; ni++) {
            int col = colBase + wn*32 + ni*8 + tig*2;
            *(float2*)&C[(size_t)r0*LDP + col]       = make_float2(c[mi][ni][0], c[mi][ni][1]);
            *(float2*)&C[(size_t)(r0 + 8)*LDP + col] = make_float2(c[mi][ni][2], c[mi][ni][3]);
        }
    }
}

// ---------------- kernel 6: attention + tanh + merge + combine (float4 smem) ----
#define ATTN_SMEM_BYTES (2*Nn*5*16 + 16)   /* 49136 + pad */
__global__ __launch_bounds__(256, 2) void attn_kernel(float* __restrict__ out) {
    extern __shared__ float4 kv4[];
    float4* Ks4 = kv4;                 // [Nn*5]
    float4* Vs4 = kv4 + Nn*5 + 1;      // keep 16B alignment; +1 pad
    int slice = blockIdx.y;
    int hb = slice / Tt, t = slice % Tt;
    int h = hb / Bb, b = hb % Bb;
    size_t sl_off = ((size_t)(b*Tt + t)*Nn)*Dd + h*HDm;
    const float* kbase = g_k2 + sl_off;
    const float* vbase = g_v2 + sl_off;
    const float* qbase = g_q2 + sl_off;
    for (int idx = threadIdx.x; idx < Nn*4; idx += 256) {
        int n = idx >> 2, q = idx & 3;
        Ks4[n*5 + q] = *(const float4*)(kbase + (size_t)n*Dd + q*4);
        Vs4[n*5 + q] = *(const float4*)(vbase + (size_t)n*Dd + q*4);
    }
    __syncthreads();

    int warp = threadIdx.x >> 5, lane = threadIdx.x & 31;
    int rstart = blockIdx.x * 77;
    int rend = min(Nn, rstart + 77);
    const float* dynb = g_dyn + (size_t)slice*SLICE_CP;

    for (int n = rstart + warp; n < rend; n += 8) {
        float4 qn[4];
        #pragma unroll
        for (int q = 0; q < 4; q++) qn[q] = *(const float4*)(qbase + (size_t)n*Dd + q*4);
        float e[10]; float mx = -1e30f;
        #pragma unroll
        for (int k = 0; k < 10; k++) {
            int m = lane + 32*k;
            float s = -1e30f;
            if (m < Nn) {
                float a = 0.f;
                #pragma unroll
                for (int q = 0; q < 4; q++) {
                    float4 km = Ks4[m*5 + q];
                    a += qn[q].x*km.x + qn[q].y*km.y + qn[q].z*km.z + qn[q].w*km.w;
                }
                s = (a * 0.25f) * dynb[(size_t)n*LDP + m];
            }
            e[k] = s; mx = fmaxf(mx, s);
        }
        #pragma unroll
        for (int o = 16; o; o >>= 1) mx = fmaxf(mx, __shfl_xor_sync(0xffffffffu, mx, o));
        float sum = 0.f;
        #pragma unroll
        for (int k = 0; k < 10; k++) { float v = __expf(e[k] - mx); e[k] = v; sum += v; }
        #pragma unroll
        for (int o = 16; o; o >>= 1) sum += __shfl_xor_sync(0xffffffffu, sum, o);
        float inv = 1.f / sum;

        float4 acc[4];
        #pragma unroll
        for (int q = 0; q < 4; q++) acc[q] = make_float4(0.f, 0.f, 0.f, 0.f);
        #pragma unroll
        for (int k = 0; k < 10; k++) {
            int m = lane + 32*k;
            if (m < Nn) {
                float w = e[k]*inv;
                #pragma unroll
                for (int q = 0; q < 4; q++) {
                    float4 vm = Vs4[m*5 + q];
                    acc[q].x += w*vm.x; acc[q].y += w*vm.y;
                    acc[q].z += w*vm.z; acc[q].w += w*vm.w;
                }
            }
        }
        float* accf = (float*)acc;
        #pragma unroll
        for (int d = 0; d < 16; d++) {
            #pragma unroll
            for (int o = 16; o; o >>= 1) accf[d] += __shfl_xor_sync(0xffffffffu, accf[d], o);
        }
        if (lane < 16) {
            size_t oidx = ((size_t)(b*Tt + t)*Nn + n)*Dd + h*HDm + lane;
            out[oidx] = g_out1h[oidx] + 0.5f * tanhf(accf[lane]);
        }
    }
}

// ---------------- launch ----------------
extern "C" void kernel_launch(void* const* d_in, const int* in_sizes, int n_in,
                              void* d_out, int out_size) {
    const float* query  = (const float*)d_in[0];
    const float* key_in = (const float*)d_in[1];
    const float* value  = (const float*)d_in[2];
    const float* adj    = (const float*)d_in[3];
    const float* Eg     = (const float*)d_in[4];
    const float* Wq     = (const float*)d_in[5];
    const float* bq     = (const float*)d_in[6];
    const float* Wk     = (const float*)d_in[7];
    const float* bk     = (const float*)d_in[8];
    const float* Wv     = (const float*)d_in[9];
    const float* bv     = (const float*)d_in[10];
    const float* Wt     = (const float*)d_in[11];
    const float* bt     = (const float*)d_in[12];
    float* out = (float*)d_out;

    cudaFuncSetAttribute(dyn_gemm_tc,
                         cudaFuncAttributeMaxDynamicSharedMemorySize, GEMM_SMEM_BYTES);
    cudaFuncSetAttribute(graphconv_tc,
                         cudaFuncAttributeMaxDynamicSharedMemorySize, GEMM_SMEM_BYTES);
    cudaFuncSetAttribute(attn_kernel,
                         cudaFuncAttributeMaxDynamicSharedMemorySize, ATTN_SMEM_BYTES);

    nadj_kernel<<<Nn, 256>>>(adj);
    egpack_kernel<<<LDP, 256>>>(Eg);
    linear_kernel<<<dim3((BTN + 63)/64, 1, 4), 256>>>(query, key_in, value,
                                                      Wq, bq, Wk, bk, Wv, bv, Wt);
    graphconv_tc<<<dim3(Bb*Tt, 3), 256, GEMM_SMEM_BYTES>>>(bt);
    pmat_kernel<<<dim3(4, NSLICE), 256>>>(query);
    dyn_gemm_tc<<<dim3(5, 3, NSLICE), 256, GEMM_SMEM_BYTES>>>();
    attn_kernel<<<dim3(4, NSLICE), 256, ATTN_SMEM_BYTES>>>(out);
}